// round 15
// baseline (speedup 1.0000x reference)
#include <cuda_runtime.h>
#include <cuda_bf16.h>
#include <cstdint>

// Swin window attention. R15 = R13 structure (best) + M=64 GEMM tiles:
// qkv/proj grids 3136, smem 33.8KB, __launch_bounds__(256,3) -> 24 warps/SM.
// Attention identical to R13 (passing, 205us).
// B=64, H=W=56, C=128, heads=4, hd=32, ws=7, L=49.

#define TOKENS   200704
#define WH_TOTAL 16384
#define QKV_ELEMS (3ull * 16384ull * 49ull * 32ull)
#define COMB_ELEMS (64 * 4 * 2401)   // [win][head][ij]
#define ATT_ELEMS ((size_t)TOKENS * 128)

__device__ float g_qkv[QKV_ELEMS];   // tf32 bits: [(s*16384 + wh)*49 + l]*32 + d
__device__ float g_att[ATT_ELEMS];   // tf32 bits: [b,h,w,c] pre-projection
__device__ float g_comb[COMB_ELEMS]; // relt[relidx[ij]][head] + mask[win][ij]

// ---------------------------------------------------------------------------
__device__ __forceinline__ uint32_t f2tf32(float x) {
    uint32_t r;
    asm("cvt.rna.tf32.f32 %0, %1;" : "=r"(r) : "f"(x));
    return r;
}
__device__ __forceinline__ void mma_tf32(float (&d)[4], const uint32_t* a, const uint32_t* b) {
    asm volatile("mma.sync.aligned.m16n8k8.row.col.f32.tf32.tf32.f32 "
                 "{%0,%1,%2,%3}, {%4,%5,%6,%7}, {%8,%9}, {%0,%1,%2,%3};"
                 : "+f"(d[0]), "+f"(d[1]), "+f"(d[2]), "+f"(d[3])
                 : "r"(a[0]), "r"(a[1]), "r"(a[2]), "r"(a[3]), "r"(b[0]), "r"(b[1]));
}

#define A_STR 132   // GEMM A smem stride (frag bank = 4g+t, conflict-free)
#define SM_A_BYTES (64 * A_STR * 4)   // 33792 (M=64 tile)

// ---------------------------------------------------------------------------
// Kernel 0: combine relative-position bias and window mask.
// ---------------------------------------------------------------------------
__global__ __launch_bounds__(256) void combine_bias(
    const int* __restrict__ relidx, const float* __restrict__ mask,
    const float* __restrict__ relt)
{
    int i = blockIdx.x * 256 + threadIdx.x;
    if (i < COMB_ELEMS) {
        int ij = i % 2401;
        int wh = i / 2401;
        int head = wh & 3, win = wh >> 2;
        g_comb[i] = __ldg(relt + __ldg(relidx + ij) * 4 + head)
                  + __ldg(mask + (size_t)win * 2401 + ij);
    }
}

// ---------------------------------------------------------------------------
// Kernel 1: QKV GEMM, M=64 tile. grid=3136, 256 threads (8 warps: 2m x 4n,
// each m-group covers 32 rows). W fragments distance-1 pipelined from gmem.
// ---------------------------------------------------------------------------
__global__ __launch_bounds__(256, 3) void qkv_gemm_mma(
    const float* __restrict__ A, const float* __restrict__ W,
    const float* __restrict__ bias)
{
    extern __shared__ uint32_t As[];

    int tid = threadIdx.x, bm = blockIdx.x;
    int lane = tid & 31, warp = tid >> 5;
    int g = lane >> 2, t = lane & 3;
    int m0 = (warp >> 2) * 32, n0 = (warp & 3) * 32;
    int head = warp & 3;

    {
        const float4* Ap = (const float4*)(A + (size_t)bm * 64 * 128);
        for (int i = tid; i < 2048; i += 256) {
            int r = i >> 5, c = (i & 31) << 2;
            float4 v = Ap[i];
            uint4 u = make_uint4(f2tf32(v.x), f2tf32(v.y), f2tf32(v.z), f2tf32(v.w));
            *(uint4*)&As[r * A_STR + c] = u;
        }
    }

    int whbase[4], lwin8[4];
#pragma unroll
    for (int mt = 0; mt < 2; mt++)
#pragma unroll
        for (int h = 0; h < 2; h++) {
            int m = bm * 64 + m0 + mt * 16 + g + h * 8;
            int bimg = m / 3136;
            int rem  = m - bimg * 3136;
            int y = rem / 56, xx = rem - y * 56;
            int nhi = y / 7,  wy = y - nhi * 7;
            int nwi = xx / 7, wx = xx - nwi * 7;
            whbase[mt * 2 + h] = (bimg * 64 + nhi * 8 + nwi) * 4 + head;
            lwin8[mt * 2 + h]  = wy * 7 + wx;
        }
    __syncthreads();

#pragma unroll 1
    for (int s = 0; s < 3; s++) {
        const float* Wp = W + s * 128 + n0 + g;
        float acc[2][4][4] = {};

        uint32_t bv[8];
        {
            const float* w0 = Wp + (size_t)t * 384;
            const float* w1 = w0 + 4 * 384;
#pragma unroll
            for (int nt = 0; nt < 4; nt++) {
                bv[nt]     = f2tf32(__ldg(w0 + nt * 8));
                bv[4 + nt] = f2tf32(__ldg(w1 + nt * 8));
            }
        }
#pragma unroll
        for (int k0 = 0; k0 < 128; k0 += 8) {
            uint32_t bc[8];
#pragma unroll
            for (int j = 0; j < 8; j++) bc[j] = bv[j];
            if (k0 < 120) {
                const float* w0 = Wp + (size_t)(k0 + 8 + t) * 384;
                const float* w1 = w0 + 4 * 384;
#pragma unroll
                for (int nt = 0; nt < 4; nt++) {
                    bv[nt]     = f2tf32(__ldg(w0 + nt * 8));
                    bv[4 + nt] = f2tf32(__ldg(w1 + nt * 8));
                }
            }
            uint32_t a[2][4];
#pragma unroll
            for (int mt = 0; mt < 2; mt++) {
                int base = (m0 + mt * 16 + g) * A_STR + k0 + t;
                a[mt][0] = As[base];
                a[mt][1] = As[base + 8 * A_STR];
                a[mt][2] = As[base + 4];
                a[mt][3] = As[base + 8 * A_STR + 4];
            }
#pragma unroll
            for (int mt = 0; mt < 2; mt++)
#pragma unroll
                for (int nt = 0; nt < 4; nt++) {
                    uint32_t bb2[2] = {bc[nt], bc[4 + nt]};
                    mma_tf32(acc[mt][nt], a[mt], bb2);
                }
        }

        float bb[4][2];
#pragma unroll
        for (int nt = 0; nt < 4; nt++) {
            int d = nt * 8 + 2 * t;
            bb[nt][0] = bias[s * 128 + head * 32 + d];
            bb[nt][1] = bias[s * 128 + head * 32 + d + 1];
        }
#pragma unroll
        for (int mt = 0; mt < 2; mt++)
#pragma unroll
            for (int h = 0; h < 2; h++) {
                int idx = mt * 2 + h;
                size_t dst0 = ((size_t)(s * 16384 + whbase[idx]) * 49 + lwin8[idx]) * 32;
#pragma unroll
                for (int nt = 0; nt < 4; nt++) {
                    int d = nt * 8 + 2 * t;
                    uint2 v = make_uint2(f2tf32(acc[mt][nt][2 * h]     + bb[nt][0]),
                                         f2tf32(acc[mt][nt][2 * h + 1] + bb[nt][1]));
                    *(uint2*)&g_qkv[dst0 + d] = v;
                }
            }
    }
}

// ---------------------------------------------------------------------------
// Kernel 3: projection GEMM, M=64 tile. grid=3136. A (g_att) raw tf32 copy.
// ---------------------------------------------------------------------------
__global__ __launch_bounds__(256, 3) void proj_gemm_mma(
    const float* __restrict__ W, const float* __restrict__ bias,
    float* __restrict__ out)
{
    extern __shared__ uint32_t As[];

    int tid = threadIdx.x, bm = blockIdx.x;
    int lane = tid & 31, warp = tid >> 5;
    int g = lane >> 2, t = lane & 3;
    int m0 = (warp >> 2) * 32, n0 = (warp & 3) * 32;

    {
        const uint4* Ap = (const uint4*)(g_att + (size_t)bm * 64 * 128);
        for (int i = tid; i < 2048; i += 256) {
            int r = i >> 5, c = (i & 31) << 2;
            *(uint4*)&As[r * A_STR + c] = Ap[i];
        }
    }
    __syncthreads();

    const float* Wp = W + n0 + g;
    float acc[2][4][4] = {};
    uint32_t bv[8];
    {
        const float* w0 = Wp + (size_t)t * 128;
        const float* w1 = w0 + 4 * 128;
#pragma unroll
        for (int nt = 0; nt < 4; nt++) {
            bv[nt]     = f2tf32(__ldg(w0 + nt * 8));
            bv[4 + nt] = f2tf32(__ldg(w1 + nt * 8));
        }
    }
#pragma unroll
    for (int k0 = 0; k0 < 128; k0 += 8) {
        uint32_t bc[8];
#pragma unroll
        for (int j = 0; j < 8; j++) bc[j] = bv[j];
        if (k0 < 120) {
            const float* w0 = Wp + (size_t)(k0 + 8 + t) * 128;
            const float* w1 = w0 + 4 * 128;
#pragma unroll
            for (int nt = 0; nt < 4; nt++) {
                bv[nt]     = f2tf32(__ldg(w0 + nt * 8));
                bv[4 + nt] = f2tf32(__ldg(w1 + nt * 8));
            }
        }
        uint32_t a[2][4];
#pragma unroll
        for (int mt = 0; mt < 2; mt++) {
            int base = (m0 + mt * 16 + g) * A_STR + k0 + t;
            a[mt][0] = As[base];
            a[mt][1] = As[base + 8 * A_STR];
            a[mt][2] = As[base + 4];
            a[mt][3] = As[base + 8 * A_STR + 4];
        }
#pragma unroll
        for (int mt = 0; mt < 2; mt++)
#pragma unroll
            for (int nt = 0; nt < 4; nt++) {
                uint32_t bb2[2] = {bc[nt], bc[4 + nt]};
                mma_tf32(acc[mt][nt], a[mt], bb2);
            }
    }

    float bb[4][2];
#pragma unroll
    for (int nt = 0; nt < 4; nt++) {
        int d = n0 + nt * 8 + 2 * t;
        bb[nt][0] = bias[d];
        bb[nt][1] = bias[d + 1];
    }
#pragma unroll
    for (int mt = 0; mt < 2; mt++)
#pragma unroll
        for (int h = 0; h < 2; h++) {
            int r = m0 + mt * 16 + g + h * 8;
            float* op = out + ((size_t)bm * 64 + r) * 128;
#pragma unroll
            for (int nt = 0; nt < 4; nt++) {
                int d = n0 + nt * 8 + 2 * t;
                float2 v = make_float2(acc[mt][nt][2 * h]     + bb[nt][0],
                                       acc[mt][nt][2 * h + 1] + bb[nt][1]);
                *(float2*)&op[d] = v;
            }
        }
}

// ---------------------------------------------------------------------------
// Kernel 2: attention (identical to R13). One block per (window, head),
// 128 threads. In-register softmax; sP aliased onto [sQ|sK].
// ---------------------------------------------------------------------------
__global__ __launch_bounds__(128) void attn_mma()
{
    __shared__ uint32_t sQK[64 * 72];  // Q (stride 36) | K; reused as P (stride 72)
    __shared__ uint32_t sV[64 * 40];

    uint32_t* sQ = sQK;
    uint32_t* sK = sQK + 2304;
    uint32_t* sP = sQK;

    int tid  = threadIdx.x;
    int lane = tid & 31, warp = tid >> 5;
    int g = lane >> 2, t = lane & 3;
    int wh   = blockIdx.x;
    int head = wh & 3;
    int widx = wh >> 2;
    int bimg = widx >> 6;
    int win  = widx & 63;
    const uint4* qp = (const uint4*)(g_qkv + (size_t)wh * 1568);
    const uint4* kp = (const uint4*)(g_qkv + (size_t)(16384 + wh) * 1568);
    const uint4* vp = (const uint4*)(g_qkv + (size_t)(2 * 16384 + wh) * 1568);
    const float* combp = g_comb + (size_t)(win * 4 + head) * 2401;

    for (int idx = tid; idx < 512; idx += 128) {
        int l = idx >> 3, c4 = (idx & 7) << 2;
        uint4 z = make_uint4(0u, 0u, 0u, 0u);
        uint4 q4 = z, k4 = z, v4 = z;
        if (l < 49) {
            int e = (l * 32 + c4) >> 2;
            q4 = qp[e]; k4 = kp[e]; v4 = vp[e];
        }
        *(uint4*)&sQ[l * 36 + c4] = q4;
        *(uint4*)&sK[l * 36 + c4] = k4;
        *(uint4*)&sV[l * 40 + c4] = v4;
    }
    __syncthreads();

    int m0 = warp * 16;

    float acc[8][4] = {};
#pragma unroll
    for (int k0 = 0; k0 < 32; k0 += 8) {
        uint32_t a[4];
        int ab = (m0 + g) * 36 + k0 + t;
        a[0] = sQ[ab];
        a[1] = sQ[ab + 8 * 36];
        a[2] = sQ[ab + 4];
        a[3] = sQ[ab + 8 * 36 + 4];
#pragma unroll
        for (int nt = 0; nt < 8; nt++) {
            uint32_t b[2];
            int bb = (nt * 8 + g) * 36 + k0 + t;
            b[0] = sK[bb];
            b[1] = sK[bb + 4];
            mma_tf32(acc[nt], a, b);
        }
    }

    float cmb[8][4];
#pragma unroll
    for (int h = 0; h < 2; h++) {
        int i = m0 + g + h * 8;
#pragma unroll
        for (int nt = 0; nt < 8; nt++)
#pragma unroll
            for (int e = 0; e < 2; e++) {
                int j = nt * 8 + 2 * t + e;
                cmb[nt][2 * h + e] = (i < 49 && j < 49)
                                   ? __ldg(combp + i * 49 + j) : -1e30f;
            }
    }

    float inv2[2];
    {
        const float scale = 0.17677669529663687f;
        float mx2[2] = {-1e30f, -1e30f};
#pragma unroll
        for (int nt = 0; nt < 8; nt++)
#pragma unroll
            for (int he = 0; he < 4; he++) {
                float v = acc[nt][he] * scale + cmb[nt][he];
                acc[nt][he] = v;
                mx2[he >> 1] = fmaxf(mx2[he >> 1], v);
            }
#pragma unroll
        for (int h = 0; h < 2; h++) {
            mx2[h] = fmaxf(mx2[h], __shfl_xor_sync(0xffffffffu, mx2[h], 1));
            mx2[h] = fmaxf(mx2[h], __shfl_xor_sync(0xffffffffu, mx2[h], 2));
        }
        float sm2[2] = {0.f, 0.f};
#pragma unroll
        for (int nt = 0; nt < 8; nt++)
#pragma unroll
            for (int he = 0; he < 4; he++) {
                float p = __expf(acc[nt][he] - mx2[he >> 1]);
                acc[nt][he] = p;
                sm2[he >> 1] += p;
            }
#pragma unroll
        for (int h = 0; h < 2; h++) {
            sm2[h] += __shfl_xor_sync(0xffffffffu, sm2[h], 1);
            sm2[h] += __shfl_xor_sync(0xffffffffu, sm2[h], 2);
        }
        inv2[0] = 1.f / sm2[0];
        inv2[1] = 1.f / sm2[1];
    }

    __syncthreads();

#pragma unroll
    for (int h = 0; h < 2; h++) {
        float inv = inv2[h];
        int row = m0 + g + h * 8;
#pragma unroll
        for (int nt = 0; nt < 8; nt++) {
            uint2 v = make_uint2(f2tf32(acc[nt][2 * h]     * inv),
                                 f2tf32(acc[nt][2 * h + 1] * inv));
            *(uint2*)&sP[row * 72 + nt * 8 + 2 * t] = v;
        }
    }
    __syncwarp();

    {
        float oac[4][4] = {};
#pragma unroll
        for (int k0 = 0; k0 < 64; k0 += 8) {
            uint32_t a[4];
            int ab = (m0 + g) * 72 + k0 + t;
            a[0] = sP[ab];
            a[1] = sP[ab + 8 * 72];
            a[2] = sP[ab + 4];
            a[3] = sP[ab + 8 * 72 + 4];
#pragma unroll
            for (int nt = 0; nt < 4; nt++) {
                uint32_t b[2];
                int bb = (k0 + t) * 40 + nt * 8 + g;
                b[0] = sV[bb];
                b[1] = sV[bb + 4 * 40];
                mma_tf32(oac[nt], a, b);
            }
        }
        int ybase = (win >> 3) * 7;
        int xbase = (win & 7) * 7;
#pragma unroll
        for (int h = 0; h < 2; h++) {
            int i = m0 + g + h * 8;
            if (i < 49) {
                int wy = i / 7, wx = i - wy * 7;
                float* op = g_att + (((size_t)(bimg * 56 + ybase + wy)) * 56 + (xbase + wx)) * 128
                          + head * 32;
#pragma unroll
                for (int nt = 0; nt < 4; nt++) {
                    uint2 v = make_uint2(f2tf32(oac[nt][2 * h]),
                                         f2tf32(oac[nt][2 * h + 1]));
                    *(uint2*)&op[nt * 8 + 2 * t] = v;
                }
            }
        }
    }
}

// ---------------------------------------------------------------------------
extern "C" void kernel_launch(void* const* d_in, const int* in_sizes, int n_in,
                              void* d_out, int out_size)
{
    const float* x      = nullptr;
    const int*   relidx = nullptr;
    const float* mask   = nullptr;
    const float* qkv_w  = nullptr;
    const float* qkv_b  = nullptr;
    const float* relt   = nullptr;
    const float* proj_w = nullptr;
    const float* proj_b = nullptr;

    for (int i = 0; i < n_in; i++) {
        switch (in_sizes[i]) {
            case 25690112: x      = (const float*)d_in[i]; break;
            case 2401:     relidx = (const int*)  d_in[i]; break;
            case 153664:   mask   = (const float*)d_in[i]; break;
            case 49152:    qkv_w  = (const float*)d_in[i]; break;
            case 384:      qkv_b  = (const float*)d_in[i]; break;
            case 676:      relt   = (const float*)d_in[i]; break;
            case 16384:    proj_w = (const float*)d_in[i]; break;
            case 128:      proj_b = (const float*)d_in[i]; break;
            default: break;
        }
    }

    cudaFuncSetAttribute(qkv_gemm_mma,  cudaFuncAttributeMaxDynamicSharedMemorySize, SM_A_BYTES);
    cudaFuncSetAttribute(proj_gemm_mma, cudaFuncAttributeMaxDynamicSharedMemorySize, SM_A_BYTES);

    combine_bias<<<(COMB_ELEMS + 255) / 256, 256>>>(relidx, mask, relt);

    qkv_gemm_mma<<<TOKENS / 64, 256, SM_A_BYTES>>>(x, qkv_w, qkv_b);

    attn_mma<<<WH_TOTAL, 128>>>();

    proj_gemm_mma<<<TOKENS / 64, 256, SM_A_BYTES>>>(proj_w, proj_b, (float*)d_out);
}

// round 16
// speedup vs baseline: 1.0877x; 1.0877x over previous
#include <cuda_runtime.h>
#include <cuda_bf16.h>
#include <cstdint>

// Swin window attention. R16 = R13 base (best, 467us) + ldmatrix A-fragments
// (qkv/proj/attn) + per-half comb processing in attention (lower reg peak).
// B=64, H=W=56, C=128, heads=4, hd=32, ws=7, L=49.

#define TOKENS   200704
#define WH_TOTAL 16384
#define QKV_ELEMS (3ull * 16384ull * 49ull * 32ull)
#define ATT_ELEMS ((size_t)TOKENS * 128)
#define COMB_ELEMS (64 * 4 * 2401)   // [win][head][ij]

__device__ float g_qkv[QKV_ELEMS];   // tf32 bits: [(s*16384 + wh)*49 + l]*32 + d
__device__ float g_att[ATT_ELEMS];   // tf32 bits: [b,h,w,c] pre-projection
__device__ float g_comb[COMB_ELEMS]; // relt[relidx[ij]][head] + mask[win][ij]

// ---------------------------------------------------------------------------
__device__ __forceinline__ uint32_t f2tf32(float x) {
    uint32_t r;
    asm("cvt.rna.tf32.f32 %0, %1;" : "=r"(r) : "f"(x));
    return r;
}
__device__ __forceinline__ void mma_tf32(float (&d)[4], const uint32_t* a, const uint32_t* b) {
    asm volatile("mma.sync.aligned.m16n8k8.row.col.f32.tf32.tf32.f32 "
                 "{%0,%1,%2,%3}, {%4,%5,%6,%7}, {%8,%9}, {%0,%1,%2,%3};"
                 : "+f"(d[0]), "+f"(d[1]), "+f"(d[2]), "+f"(d[3])
                 : "r"(a[0]), "r"(a[1]), "r"(a[2]), "r"(a[3]), "r"(b[0]), "r"(b[1]));
}
// ldmatrix x4: loads the full m16k16 A-fragment (a[0..3]) in one instruction.
// Lane i supplies the row address: matrix = i>>3, row-in-matrix = i&7.
__device__ __forceinline__ void ldsm_x4(uint32_t (&r)[4], const uint32_t* p) {
    uint32_t a = (uint32_t)__cvta_generic_to_shared(p);
    asm volatile("ldmatrix.sync.aligned.m8n8.x4.shared.b16 {%0,%1,%2,%3}, [%4];"
                 : "=r"(r[0]), "=r"(r[1]), "=r"(r[2]), "=r"(r[3]) : "r"(a));
}
// Per-lane word offset of this lane's ldmatrix row for an A-frag tile at
// (row0, k0=0) with row stride STR: row = row0 + (lane&15), col = (lane>>4)*4.
__device__ __forceinline__ int ldsm_off(int lane, int row0, int stride) {
    return (row0 + (lane & 15)) * stride + ((lane >> 4) << 2);
}

#define A_STR 132   // GEMM A smem stride (frag bank = 4g+t, conflict-free)
#define SM_A_BYTES (128 * A_STR * 4)   // 67584

// ---------------------------------------------------------------------------
// Kernel 0: combine relative-position bias and window mask.
// ---------------------------------------------------------------------------
__global__ __launch_bounds__(256) void combine_bias(
    const int* __restrict__ relidx, const float* __restrict__ mask,
    const float* __restrict__ relt)
{
    int i = blockIdx.x * 256 + threadIdx.x;
    if (i < COMB_ELEMS) {
        int ij = i % 2401;
        int wh = i / 2401;
        int head = wh & 3, win = wh >> 2;
        g_comb[i] = __ldg(relt + __ldg(relidx + ij) * 4 + head)
                  + __ldg(mask + (size_t)win * 2401 + ij);
    }
}

// ---------------------------------------------------------------------------
// Kernel 1: QKV GEMM. grid=1568, 256 threads (8 warps: 2m x 4n). A in smem,
// W fragments distance-1 pipelined from gmem. A-frags via ldmatrix.
// ---------------------------------------------------------------------------
__global__ __launch_bounds__(256, 2) void qkv_gemm_mma(
    const float* __restrict__ A, const float* __restrict__ W,
    const float* __restrict__ bias)
{
    extern __shared__ uint32_t As[];

    int tid = threadIdx.x, bm = blockIdx.x;
    int lane = tid & 31, warp = tid >> 5;
    int g = lane >> 2, t = lane & 3;
    int m0 = (warp >> 2) * 64, n0 = (warp & 3) * 32;
    int head = warp & 3;

    {
        const float4* Ap = (const float4*)(A + (size_t)bm * 128 * 128);
        for (int i = tid; i < 4096; i += 256) {
            int r = i >> 5, c = (i & 31) << 2;
            float4 v = Ap[i];
            uint4 u = make_uint4(f2tf32(v.x), f2tf32(v.y), f2tf32(v.z), f2tf32(v.w));
            *(uint4*)&As[r * A_STR + c] = u;
        }
    }

    int whbase[8], lwin8[8];
#pragma unroll
    for (int mt = 0; mt < 4; mt++)
#pragma unroll
        for (int h = 0; h < 2; h++) {
            int m = bm * 128 + m0 + mt * 16 + g + h * 8;
            int bimg = m / 3136;
            int rem  = m - bimg * 3136;
            int y = rem / 56, xx = rem - y * 56;
            int nhi = y / 7,  wy = y - nhi * 7;
            int nwi = xx / 7, wx = xx - nwi * 7;
            whbase[mt * 2 + h] = (bimg * 64 + nhi * 8 + nwi) * 4 + head;
            lwin8[mt * 2 + h]  = wy * 7 + wx;
        }

    // per-mt ldmatrix lane base offsets
    int aoff[4];
#pragma unroll
    for (int mt = 0; mt < 4; mt++)
        aoff[mt] = ldsm_off(lane, m0 + mt * 16, A_STR);
    __syncthreads();

#pragma unroll 1
    for (int s = 0; s < 3; s++) {
        const float* Wp = W + s * 128 + n0 + g;
        float acc[4][4][4] = {};

        uint32_t bv[8];
        {
            const float* w0 = Wp + (size_t)t * 384;
            const float* w1 = w0 + 4 * 384;
#pragma unroll
            for (int nt = 0; nt < 4; nt++) {
                bv[nt]     = f2tf32(__ldg(w0 + nt * 8));
                bv[4 + nt] = f2tf32(__ldg(w1 + nt * 8));
            }
        }
#pragma unroll
        for (int k0 = 0; k0 < 128; k0 += 8) {
            uint32_t bc[8];
#pragma unroll
            for (int j = 0; j < 8; j++) bc[j] = bv[j];
            if (k0 < 120) {
                const float* w0 = Wp + (size_t)(k0 + 8 + t) * 384;
                const float* w1 = w0 + 4 * 384;
#pragma unroll
                for (int nt = 0; nt < 4; nt++) {
                    bv[nt]     = f2tf32(__ldg(w0 + nt * 8));
                    bv[4 + nt] = f2tf32(__ldg(w1 + nt * 8));
                }
            }
            uint32_t a[4][4];
#pragma unroll
            for (int mt = 0; mt < 4; mt++)
                ldsm_x4(a[mt], As + aoff[mt] + k0);
#pragma unroll
            for (int mt = 0; mt < 4; mt++)
#pragma unroll
                for (int nt = 0; nt < 4; nt++) {
                    uint32_t bb2[2] = {bc[nt], bc[4 + nt]};
                    mma_tf32(acc[mt][nt], a[mt], bb2);
                }
        }

        float bb[4][2];
#pragma unroll
        for (int nt = 0; nt < 4; nt++) {
            int d = nt * 8 + 2 * t;
            bb[nt][0] = bias[s * 128 + head * 32 + d];
            bb[nt][1] = bias[s * 128 + head * 32 + d + 1];
        }
#pragma unroll
        for (int mt = 0; mt < 4; mt++)
#pragma unroll
            for (int h = 0; h < 2; h++) {
                int idx = mt * 2 + h;
                size_t dst0 = ((size_t)(s * 16384 + whbase[idx]) * 49 + lwin8[idx]) * 32;
#pragma unroll
                for (int nt = 0; nt < 4; nt++) {
                    int d = nt * 8 + 2 * t;
                    uint2 v = make_uint2(f2tf32(acc[mt][nt][2 * h]     + bb[nt][0]),
                                         f2tf32(acc[mt][nt][2 * h + 1] + bb[nt][1]));
                    *(uint2*)&g_qkv[dst0 + d] = v;
                }
            }
    }
}

// ---------------------------------------------------------------------------
// Kernel 3: projection GEMM. A (g_att) raw tf32 copy; A-frags via ldmatrix.
// ---------------------------------------------------------------------------
__global__ __launch_bounds__(256, 2) void proj_gemm_mma(
    const float* __restrict__ W, const float* __restrict__ bias,
    float* __restrict__ out)
{
    extern __shared__ uint32_t As[];

    int tid = threadIdx.x, bm = blockIdx.x;
    int lane = tid & 31, warp = tid >> 5;
    int g = lane >> 2, t = lane & 3;
    int m0 = (warp >> 2) * 64, n0 = (warp & 3) * 32;

    {
        const uint4* Ap = (const uint4*)(g_att + (size_t)bm * 128 * 128);
        for (int i = tid; i < 4096; i += 256) {
            int r = i >> 5, c = (i & 31) << 2;
            *(uint4*)&As[r * A_STR + c] = Ap[i];
        }
    }
    int aoff[4];
#pragma unroll
    for (int mt = 0; mt < 4; mt++)
        aoff[mt] = ldsm_off(lane, m0 + mt * 16, A_STR);
    __syncthreads();

    const float* Wp = W + n0 + g;
    float acc[4][4][4] = {};
    uint32_t bv[8];
    {
        const float* w0 = Wp + (size_t)t * 128;
        const float* w1 = w0 + 4 * 128;
#pragma unroll
        for (int nt = 0; nt < 4; nt++) {
            bv[nt]     = f2tf32(__ldg(w0 + nt * 8));
            bv[4 + nt] = f2tf32(__ldg(w1 + nt * 8));
        }
    }
#pragma unroll
    for (int k0 = 0; k0 < 128; k0 += 8) {
        uint32_t bc[8];
#pragma unroll
        for (int j = 0; j < 8; j++) bc[j] = bv[j];
        if (k0 < 120) {
            const float* w0 = Wp + (size_t)(k0 + 8 + t) * 128;
            const float* w1 = w0 + 4 * 128;
#pragma unroll
            for (int nt = 0; nt < 4; nt++) {
                bv[nt]     = f2tf32(__ldg(w0 + nt * 8));
                bv[4 + nt] = f2tf32(__ldg(w1 + nt * 8));
            }
        }
        uint32_t a[4][4];
#pragma unroll
        for (int mt = 0; mt < 4; mt++)
            ldsm_x4(a[mt], As + aoff[mt] + k0);
#pragma unroll
        for (int mt = 0; mt < 4; mt++)
#pragma unroll
            for (int nt = 0; nt < 4; nt++) {
                uint32_t bb2[2] = {bc[nt], bc[4 + nt]};
                mma_tf32(acc[mt][nt], a[mt], bb2);
            }
    }

    float bb[4][2];
#pragma unroll
    for (int nt = 0; nt < 4; nt++) {
        int d = n0 + nt * 8 + 2 * t;
        bb[nt][0] = bias[d];
        bb[nt][1] = bias[d + 1];
    }
#pragma unroll
    for (int mt = 0; mt < 4; mt++)
#pragma unroll
        for (int h = 0; h < 2; h++) {
            int r = m0 + mt * 16 + g + h * 8;
            float* op = out + ((size_t)bm * 128 + r) * 128;
#pragma unroll
            for (int nt = 0; nt < 4; nt++) {
                int d = n0 + nt * 8 + 2 * t;
                float2 v = make_float2(acc[mt][nt][2 * h]     + bb[nt][0],
                                       acc[mt][nt][2 * h + 1] + bb[nt][1]);
                *(float2*)&op[d] = v;
            }
        }
}

// ---------------------------------------------------------------------------
// Kernel 2: attention. One block per (window, head), 128 threads.
// In-register softmax; sP aliased onto [sQ|sK]; ldmatrix a-frags.
// ---------------------------------------------------------------------------
__global__ __launch_bounds__(128) void attn_mma()
{
    __shared__ uint32_t sQK[64 * 72];  // Q (stride 36) | K; reused as P (stride 72)
    __shared__ uint32_t sV[64 * 40];

    uint32_t* sQ = sQK;
    uint32_t* sK = sQK + 2304;
    uint32_t* sP = sQK;

    int tid  = threadIdx.x;
    int lane = tid & 31, warp = tid >> 5;
    int g = lane >> 2, t = lane & 3;
    int wh   = blockIdx.x;
    int head = wh & 3;
    int widx = wh >> 2;
    int bimg = widx >> 6;
    int win  = widx & 63;
    const uint4* qp = (const uint4*)(g_qkv + (size_t)wh * 1568);
    const uint4* kp = (const uint4*)(g_qkv + (size_t)(16384 + wh) * 1568);
    const uint4* vp = (const uint4*)(g_qkv + (size_t)(2 * 16384 + wh) * 1568);
    const float* combp = g_comb + (size_t)(win * 4 + head) * 2401;

    for (int idx = tid; idx < 512; idx += 128) {
        int l = idx >> 3, c4 = (idx & 7) << 2;
        uint4 z = make_uint4(0u, 0u, 0u, 0u);
        uint4 q4 = z, k4 = z, v4 = z;
        if (l < 49) {
            int e = (l * 32 + c4) >> 2;
            q4 = qp[e]; k4 = kp[e]; v4 = vp[e];
        }
        *(uint4*)&sQ[l * 36 + c4] = q4;
        *(uint4*)&sK[l * 36 + c4] = k4;
        *(uint4*)&sV[l * 40 + c4] = v4;
    }
    __syncthreads();

    int m0 = warp * 16;
    int qoff = ldsm_off(lane, m0, 36);
    int poff = ldsm_off(lane, m0, 72);

    float acc[8][4] = {};
#pragma unroll
    for (int k0 = 0; k0 < 32; k0 += 8) {
        uint32_t a[4];
        ldsm_x4(a, sQ + qoff + k0);
#pragma unroll
        for (int nt = 0; nt < 8; nt++) {
            uint32_t b[2];
            int bb = (nt * 8 + g) * 36 + k0 + t;
            b[0] = sK[bb];
            b[1] = sK[bb + 4];
            mma_tf32(acc[nt], a, b);
        }
    }

    // ---- softmax, comb processed per h-half (16 transient regs) ----
    float inv2[2];
    {
        const float scale = 0.17677669529663687f;
        float mx2[2], sm2[2];
#pragma unroll
        for (int h = 0; h < 2; h++) {
            int i = m0 + g + h * 8;
            float c[8][2];
#pragma unroll
            for (int nt = 0; nt < 8; nt++)
#pragma unroll
                for (int e = 0; e < 2; e++) {
                    int j = nt * 8 + 2 * t + e;
                    c[nt][e] = (i < 49 && j < 49)
                             ? __ldg(combp + i * 49 + j) : -1e30f;
                }
            float mx = -1e30f;
#pragma unroll
            for (int nt = 0; nt < 8; nt++)
#pragma unroll
                for (int e = 0; e < 2; e++) {
                    float v = acc[nt][2 * h + e] * scale + c[nt][e];
                    acc[nt][2 * h + e] = v;
                    mx = fmaxf(mx, v);
                }
            mx = fmaxf(mx, __shfl_xor_sync(0xffffffffu, mx, 1));
            mx = fmaxf(mx, __shfl_xor_sync(0xffffffffu, mx, 2));
            mx2[h] = mx;
        }
#pragma unroll
        for (int h = 0; h < 2; h++) {
            float sum = 0.f;
#pragma unroll
            for (int nt = 0; nt < 8; nt++)
#pragma unroll
                for (int e = 0; e < 2; e++) {
                    float p = __expf(acc[nt][2 * h + e] - mx2[h]);
                    acc[nt][2 * h + e] = p;
                    sum += p;
                }
            sum += __shfl_xor_sync(0xffffffffu, sum, 1);
            sum += __shfl_xor_sync(0xffffffffu, sum, 2);
            sm2[h] = sum;
        }
        inv2[0] = 1.f / sm2[0];
        inv2[1] = 1.f / sm2[1];
    }

    __syncthreads();   // all warps done reading sQ/sK before P overwrites

#pragma unroll
    for (int h = 0; h < 2; h++) {
        float inv = inv2[h];
        int row = m0 + g + h * 8;
#pragma unroll
        for (int nt = 0; nt < 8; nt++) {
            uint2 v = make_uint2(f2tf32(acc[nt][2 * h]     * inv),
                                 f2tf32(acc[nt][2 * h + 1] * inv));
            *(uint2*)&sP[row * 72 + nt * 8 + 2 * t] = v;
        }
    }
    __syncwarp();

    {
        float oac[4][4] = {};
#pragma unroll
        for (int k0 = 0; k0 < 64; k0 += 8) {
            uint32_t a[4];
            ldsm_x4(a, sP + poff + k0);
#pragma unroll
            for (int nt = 0; nt < 4; nt++) {
                uint32_t b[2];
                int bb = (k0 + t) * 40 + nt * 8 + g;
                b[0] = sV[bb];
                b[1] = sV[bb + 4 * 40];
                mma_tf32(oac[nt], a, b);
            }
        }
        int ybase = (win >> 3) * 7;
        int xbase = (win & 7) * 7;
#pragma unroll
        for (int h = 0; h < 2; h++) {
            int i = m0 + g + h * 8;
            if (i < 49) {
                int wy = i / 7, wx = i - wy * 7;
                float* op = g_att + (((size_t)(bimg * 56 + ybase + wy)) * 56 + (xbase + wx)) * 128
                          + head * 32;
#pragma unroll
                for (int nt = 0; nt < 4; nt++) {
                    uint2 v = make_uint2(f2tf32(oac[nt][2 * h]),
                                         f2tf32(oac[nt][2 * h + 1]));
                    *(uint2*)&op[nt * 8 + 2 * t] = v;
                }
            }
        }
    }
}

// ---------------------------------------------------------------------------
extern "C" void kernel_launch(void* const* d_in, const int* in_sizes, int n_in,
                              void* d_out, int out_size)
{
    const float* x      = nullptr;
    const int*   relidx = nullptr;
    const float* mask   = nullptr;
    const float* qkv_w  = nullptr;
    const float* qkv_b  = nullptr;
    const float* relt   = nullptr;
    const float* proj_w = nullptr;
    const float* proj_b = nullptr;

    for (int i = 0; i < n_in; i++) {
        switch (in_sizes[i]) {
            case 25690112: x      = (const float*)d_in[i]; break;
            case 2401:     relidx = (const int*)  d_in[i]; break;
            case 153664:   mask   = (const float*)d_in[i]; break;
            case 49152:    qkv_w  = (const float*)d_in[i]; break;
            case 384:      qkv_b  = (const float*)d_in[i]; break;
            case 676:      relt   = (const float*)d_in[i]; break;
            case 16384:    proj_w = (const float*)d_in[i]; break;
            case 128:      proj_b = (const float*)d_in[i]; break;
            default: break;
        }
    }

    cudaFuncSetAttribute(qkv_gemm_mma,  cudaFuncAttributeMaxDynamicSharedMemorySize, SM_A_BYTES);
    cudaFuncSetAttribute(proj_gemm_mma, cudaFuncAttributeMaxDynamicSharedMemorySize, SM_A_BYTES);

    combine_bias<<<(COMB_ELEMS + 255) / 256, 256>>>(relidx, mask, relt);

    qkv_gemm_mma<<<TOKENS / 128, 256, SM_A_BYTES>>>(x, qkv_w, qkv_b);

    attn_mma<<<WH_TOTAL, 128>>>();

    proj_gemm_mma<<<TOKENS / 128, 256, SM_A_BYTES>>>(proj_w, proj_b, (float*)d_out);
}